// round 14
// baseline (speedup 1.0000x reference)
#include <cuda_runtime.h>
#include <cuda_bf16.h>
#include <cstdint>

// ---------------------------------------------------------------------------
// Shapes (fixed by the bench)
// ---------------------------------------------------------------------------
#define BATCH 16
#define TLEN  2048
#define CDIM  200
#define DDIM  2048
#define MPAD  256              // compacted class rows per batch (padded)

// GEMM: swapped operands (A = feats, M = 128 dense d-rows; B = mask,
// N = nact classes), 16 warps as 4m x 4n (warp 32x32), hybrid K tasks,
// 3-stage smem pipeline with convert-at-load (tail-hiding).
#define KC      64             // k per smem chunk (64 bf16 = 128B SW128 row)
#define NTILE   128            // d rows per CTA (M)
#define NTASKS  256            // 16 dtiles x 16 batches
#define NFULL   148            // full-K tasks = exactly wave 1 (one per SM)
#define NQUART  ((NTASKS - NFULL) * 4)   // 432 quarter-K tasks
#define QCHUNKS 8              // chunks per quarter task (2048/64/4)

// smem: 3 stages x (16KB mask + 16KB feats) = 96KB
#define SM_MASK(st) ((st) * 16384)
#define SM_FEAT(st) (49152 + (st) * 16384)
#define SMEM_BYTES 98304

// ---------------------------------------------------------------------------
// Scratch — device symbols ONLY, never passed from host (ATS shadow trap!)
// ---------------------------------------------------------------------------
__device__ __align__(128) __nv_bfloat16 g_Amat[(size_t)BATCH * MPAD * TLEN]; // 16MB
__device__ float g_sums[MPAD * DDIM];   // indexed by TRUE class (0..199)
__device__ int   g_counts[MPAD];
__device__ int   g_clist[BATCH * MPAD]; // compact j -> true class c
__device__ int   g_cmap[BATCH * MPAD];  // true class c -> compact j (or -1)
__device__ int   g_nact[BATCH];

// ---------------------------------------------------------------------------
// helpers
// ---------------------------------------------------------------------------
__device__ __forceinline__ uint32_t smem_u32(const void* p) {
    uint32_t a;
    asm("{ .reg .u64 t; cvta.to.shared.u64 t, %1; cvt.u32.u64 %0, t; }"
        : "=r"(a) : "l"(p));
    return a;
}
__device__ __forceinline__ uint32_t sw128(uint32_t off) {
    return off ^ ((off >> 3) & 0x70);
}
__device__ __forceinline__ void sts128(uint32_t a, uint32_t x, uint32_t y,
                                       uint32_t z, uint32_t w) {
    asm volatile("st.shared.v4.b32 [%0], {%1,%2,%3,%4};"
                 :: "r"(a), "r"(x), "r"(y), "r"(z), "r"(w) : "memory");
}
__device__ __forceinline__ uint32_t pack_bf16x2(float lo, float hi) {
    uint32_t r;
    asm("cvt.rn.satfinite.bf16x2.f32 %0, %1, %2;" : "=r"(r) : "f"(hi), "f"(lo));
    return r;
}
__device__ __forceinline__ void cp_async16(uint32_t saddr, const void* gaddr) {
    asm volatile("cp.async.cg.shared.global [%0], [%1], 16;"
                 :: "r"(saddr), "l"(gaddr) : "memory");
}
__device__ __forceinline__ void cp_commit() {
    asm volatile("cp.async.commit_group;" ::: "memory");
}
__device__ __forceinline__ void cp_wait0() {
    asm volatile("cp.async.wait_group 0;" ::: "memory");
}
__device__ __forceinline__ void cp_wait1() {
    asm volatile("cp.async.wait_group 1;" ::: "memory");
}
__device__ __forceinline__ void ldmatrix_x4(uint32_t* r, uint32_t addr) {
    asm volatile("ldmatrix.sync.aligned.m8n8.x4.shared.b16 {%0,%1,%2,%3}, [%4];"
                 : "=r"(r[0]), "=r"(r[1]), "=r"(r[2]), "=r"(r[3]) : "r"(addr));
}
__device__ __forceinline__ void mma16816(float* c, const uint32_t* a,
                                         uint32_t b0, uint32_t b1) {
    asm volatile(
        "mma.sync.aligned.m16n8k16.row.col.f32.bf16.bf16.f32 "
        "{%0,%1,%2,%3}, {%4,%5,%6,%7}, {%8,%9}, {%0,%1,%2,%3};"
        : "+f"(c[0]), "+f"(c[1]), "+f"(c[2]), "+f"(c[3])
        : "r"(a[0]), "r"(a[1]), "r"(a[2]), "r"(a[3]), "r"(b0), "r"(b1));
}

// ---------------------------------------------------------------------------
// Stage 0: blocks 0..15 per-batch class compaction; blocks 16+ zero sums +
// counts. The sums-zero here is load-bearing: it warms L2 with the g_sums
// lines right before the GEMM's atomics (removing it cost +42us in R10).
// ---------------------------------------------------------------------------
#define SUMS_U4 (MPAD * DDIM * 4 / 16)   // 131072
#define PREP_BLOCKS (BATCH + (SUMS_U4 + 255) / 256)
__global__ __launch_bounds__(256) void prep_kernel(const int* __restrict__ vid) {
    if (blockIdx.x >= BATCH) {
        int i = (blockIdx.x - BATCH) * 256 + threadIdx.x;
        const uint4 z = {0, 0, 0, 0};
        if (i < SUMS_U4) ((uint4*)g_sums)[i] = z;
        if (i < MPAD) g_counts[i] = 0;
        return;
    }
    __shared__ int warp_sums[8];
    __shared__ int warp_base[8];
    int b = blockIdx.x, tid = threadIdx.x;
    int lid = tid & 31, wid = tid >> 5;

    int flag = (tid < CDIM) ? (vid[b * CDIM + tid] != 0) : 0;
    uint32_t bal = __ballot_sync(0xFFFFFFFFu, flag);
    if (lid == 0) warp_sums[wid] = __popc(bal);
    __syncthreads();
    if (tid == 0) {
        int run = 0;
        for (int w = 0; w < 8; w++) { warp_base[w] = run; run += warp_sums[w]; }
        g_nact[b] = run;
    }
    __syncthreads();
    int j = warp_base[wid] + __popc(bal & ((1u << lid) - 1));
    if (flag) {
        g_cmap[b * MPAD + tid] = j;
        g_clist[b * MPAD + j] = tid;
    } else {
        g_cmap[b * MPAD + tid] = -1;
    }
}

// ---------------------------------------------------------------------------
// Stage 1: compacted bf16 mask Amat[b][j][t] + per-class counts.
// (verified-fast R9 version — unchanged)
// ---------------------------------------------------------------------------
__global__ __launch_bounds__(256) void build_mask_kernel(const int* __restrict__ act) {
    __shared__ __nv_bfloat16 m[CDIM][66];   // only rows < nact are written/read

    int tid = threadIdx.x;
    int b = blockIdx.x >> 5;
    int t0 = (blockIdx.x & 31) * 64;
    int nact = g_nact[b];
    int j = (tid < CDIM) ? g_cmap[b * MPAD + tid] : -1;

    const __nv_bfloat16 one = __float2bfloat16(1.0f);
    const __nv_bfloat16 zero = __float2bfloat16(0.0f);

    const int* ap = act + ((size_t)b * TLEN + t0) * CDIM + tid;
    int cnt = 0;
    if (j >= 0) {
#pragma unroll 1
        for (int p = 0; p < 8; p++) {
            int vr[8];
#pragma unroll
            for (int u = 0; u < 8; u++)          // 8 coalesced loads in flight
                vr[u] = ap[(size_t)(p * 8 + u) * CDIM];
#pragma unroll
            for (int u = 0; u < 8; u++) {
                bool on = vr[u] != 0;
                m[j][p * 8 + u] = on ? one : zero;
                cnt += on;
            }
        }
        if (cnt) atomicAdd(&g_counts[tid], cnt);
    }
    __syncthreads();

    int lid = tid & 31, wid = tid >> 5;
    for (int jj = wid; jj < nact; jj += 8) {
        uint32_t v = *(const uint32_t*)&m[jj][2 * lid];
        *(uint32_t*)((char*)g_Amat +
                     ((size_t)(b * MPAD + jj) * TLEN + t0 + 2 * lid) * 2) = v;
    }
}

// ---------------------------------------------------------------------------
// Static-NT compute body (warp tile m32 x n32): per ks, 2 A ldsm + NB B ldsm
// + 2*NT mma. NT compile-time -> clean static scheduling.
// ---------------------------------------------------------------------------
template <int NT>
__device__ __forceinline__ void compute_t(uint32_t mask_base, uint32_t feat_base,
                                          const uint32_t* a_off,
                                          const uint32_t* b_off,
                                          float acc[2][4][4]) {
    constexpr int NB = (NT + 1) >> 1;
#pragma unroll
    for (int ks = 0; ks < 4; ks++) {
        uint32_t a[2][4], bf[NB][4];
#pragma unroll
        for (int mt = 0; mt < 2; mt++)
            ldmatrix_x4(a[mt], feat_base + sw128(a_off[mt] + ks * 32));
#pragma unroll
        for (int nb = 0; nb < NB; nb++)
            ldmatrix_x4(bf[nb], mask_base + sw128(b_off[nb] + ks * 32));
#pragma unroll
        for (int mt = 0; mt < 2; mt++)
#pragma unroll
            for (int nt = 0; nt < NT; nt++)
                mma16816(acc[mt][nt], a[mt],
                         bf[nt >> 1][(nt & 1) * 2], bf[nt >> 1][(nt & 1) * 2 + 1]);
    }
}

// ---------------------------------------------------------------------------
// Stage 2: per-batch bf16 GEMM, 3-stage pipeline with convert-at-load.
// Per chunk i the barrier-critical path is wait+sync only: STS for chunk i+1
// is issued BEFORE compute(i) (its stage was drained by the i-1 barrier) and
// cp.async for chunk i+2 stays in flight across the barrier (wait_group 1).
// ---------------------------------------------------------------------------
__global__ __launch_bounds__(512, 1) void gemm_kernel(const float* __restrict__ feats) {
    int task, ck0, nch;
    if (blockIdx.x < NFULL) {
        task = blockIdx.x;           ck0 = 0;                 nch = 32;
    } else {
        int r = blockIdx.x - NFULL;
        task = NFULL + (r >> 2);     ck0 = (r & 3) * QCHUNKS; nch = QCHUNKS;
    }
    const int b = task & 15;
    const int d0 = (task >> 4) * NTILE;
    const int nbase = blockIdx.y * 128;     // class window base (2nd CTA rare)
    const int nact = g_nact[b];
    if (nbase >= nact) return;
    const int nlim = nact - nbase;          // classes in this CTA's window

    extern __shared__ char smem[];
    const uint32_t sb = smem_u32(smem);
    const int tid = threadIdx.x;
    const int lane = tid & 31, wid = tid >> 5;
    const int wm = wid & 3;             // m: d rows wm*32 (dense) — SMSP id
    const int wn = wid >> 2;            // n: class cols wn*32

    const int nrem = nlim - wn * 32;
    const int ncap = nrem < 32 ? (nrem > 0 ? nrem : 0) : 32;
    const int ntmax = (ncap + 7) >> 3;          // 0..4

    const int dcol = tid & 127;
    const int kq = tid >> 7;            // 0..3 -> k = kq*16 .. +15

    float acc[2][4][4];
#pragma unroll
    for (int mt = 0; mt < 2; mt++)
#pragma unroll
        for (int i = 0; i < 4; i++)
#pragma unroll
            for (int r = 0; r < 4; r++) acc[mt][i][r] = 0.0f;

    uint32_t a_off[2];
#pragma unroll
    for (int mt = 0; mt < 2; mt++) {
        int rowA = wm * 32 + mt * 16 + (lane & 15);
        a_off[mt] = (uint32_t)(rowA * 128 + (lane >> 4) * 16);
    }
    uint32_t b_off[2];
#pragma unroll
    for (int nb = 0; nb < 2; nb++) {
        int rowB = wn * 32 + nb * 16 + ((lane >> 4) << 3) + (lane & 7);
        b_off[nb] = (uint32_t)(rowB * 128 + ((lane >> 3) & 1) * 16);
    }

    const __nv_bfloat16* abase_g = g_Amat + (size_t)(b * MPAD + nbase) * TLEN;
    const float* fbase = feats + (size_t)b * TLEN * DDIM;

    uint32_t pb[2][8];   // converted feats for chunks (c-ck0) even/odd

    auto cpA = [&](int ck, int st) {     // mask tile -> stage st (+ commit)
        const int k0 = ck * KC;
        const uint32_t abase = sb + SM_MASK(st);
#pragma unroll
        for (int it = 0; it < 2; it++) {
            int idx = it * 512 + tid;
            int row = idx >> 3, seg = idx & 7;
            if (row < nlim) {
                const void* g = abase_g + (size_t)row * TLEN + k0 + seg * 8;
                cp_async16(abase + sw128((uint32_t)(row * 128 + seg * 16)), g);
            }
        }
        cp_commit();
    };
    auto ldgcvt = [&](int ck, uint32_t* p) {   // feats LDG + f32->bf16 pack
        const float* fp = fbase + (size_t)(ck * KC + kq * 16) * DDIM + d0 + dcol;
        float f[16];
#pragma unroll
        for (int jj = 0; jj < 16; jj++) f[jj] = fp[(size_t)jj * DDIM];
#pragma unroll
        for (int jj = 0; jj < 8; jj++) p[jj] = pack_bf16x2(f[2 * jj], f[2 * jj + 1]);
    };
    auto stsB = [&](int st, const uint32_t* p) {
        const uint32_t bbase = sb + SM_FEAT(st);
        uint32_t o0 = (uint32_t)(dcol * 128 + kq * 32);
        sts128(bbase + sw128(o0), p[0], p[1], p[2], p[3]);
        sts128(bbase + sw128(o0 + 16), p[4], p[5], p[6], p[7]);
    };
    auto compute = [&](int st) {
        const uint32_t mask_base = sb + SM_MASK(st);
        const uint32_t feat_base = sb + SM_FEAT(st);
        switch (ntmax) {
            case 4: compute_t<4>(mask_base, feat_base, a_off, b_off, acc); break;
            case 3: compute_t<3>(mask_base, feat_base, a_off, b_off, acc); break;
            case 2: compute_t<2>(mask_base, feat_base, a_off, b_off, acc); break;
            case 1: compute_t<1>(mask_base, feat_base, a_off, b_off, acc); break;
            default: break;
        }
    };

    // prologue: chunk0 fully staged; chunk1 mask in flight + feats in regs
    cpA(ck0, 0);
    ldgcvt(ck0, pb[0]);
    cpA(ck0 + 1, 1);
    stsB(0, pb[0]);
    ldgcvt(ck0 + 1, pb[1]);
    cp_wait1();                 // A(chunk0) done; A(chunk1) may be in flight
    __syncthreads();

#pragma unroll 1
    for (int i = 0; i < nch; i++) {
        const int s = i % 3;
        if (i + 2 < nch) cpA(ck0 + i + 2, (i + 2) % 3);
        if (i + 1 < nch) stsB((i + 1) % 3, pb[(i + 1) & 1]);
        if (i + 2 < nch) ldgcvt(ck0 + i + 2, pb[i & 1]);
        compute(s);
        if (i + 1 < nch) {
            if (i + 2 < nch) cp_wait1(); else cp_wait0();
            __syncthreads();
        }
    }

    // epilogue: fragment rows = d (dense), cols = compact classes -> scatter
    {
        const int col2 = (lane & 3) * 2;
        const int* clist = g_clist + b * MPAD;
#pragma unroll
        for (int mt = 0; mt < 2; mt++) {
            const int dd = d0 + wm * 32 + mt * 16 + (lane >> 2);
#pragma unroll
            for (int nt = 0; nt < 4; nt++) {
                if (nt >= ntmax) break;
                int jn = nbase + wn * 32 + nt * 8 + col2;
                int c0 = (jn < nact) ? clist[jn] : -1;
                int c1 = (jn + 1 < nact) ? clist[jn + 1] : -1;
                if (c0 >= 0) {
                    float* gp = g_sums + (size_t)c0 * DDIM + dd;
                    atomicAdd(gp, acc[mt][nt][0]);
                    atomicAdd(gp + 8, acc[mt][nt][2]);
                }
                if (c1 >= 0) {
                    float* gp = g_sums + (size_t)c1 * DDIM + dd;
                    atomicAdd(gp, acc[mt][nt][1]);
                    atomicAdd(gp + 8, acc[mt][nt][3]);
                }
            }
        }
    }
}

// ---------------------------------------------------------------------------
// Stage 3: momentum update — 2 independent float4 chains per thread (ILP)
// ---------------------------------------------------------------------------
#define FIN_HALF (CDIM * DDIM / 4 / 2)   // 51200
__global__ void finalize_kernel(const float4* __restrict__ proto,
                                float4* __restrict__ out) {
    int i = blockIdx.x * 256 + threadIdx.x;
    if (i >= FIN_HALF) return;
    int i2 = i + FIN_HALF;
    int ca = i >> 9, cb = i2 >> 9;
    float4 pa = proto[i], pb = proto[i2];
    float4 sa = ((const float4*)g_sums)[i], sb = ((const float4*)g_sums)[i2];
    int na = g_counts[ca], nb = g_counts[cb];
    float ia = 0.001f / fmaxf((float)na, 1.0f);
    float ib = 0.001f / fmaxf((float)nb, 1.0f);
    float4 ra, rb;
    ra.x = 0.999f * pa.x + sa.x * ia;  ra.y = 0.999f * pa.y + sa.y * ia;
    ra.z = 0.999f * pa.z + sa.z * ia;  ra.w = 0.999f * pa.w + sa.w * ia;
    rb.x = 0.999f * pb.x + sb.x * ib;  rb.y = 0.999f * pb.y + sb.y * ib;
    rb.z = 0.999f * pb.z + sb.z * ib;  rb.w = 0.999f * pb.w + sb.w * ib;
    out[i]  = (na > 0) ? ra : pa;
    out[i2] = (nb > 0) ? rb : pb;
}

// ---------------------------------------------------------------------------
// Launch
// ---------------------------------------------------------------------------
extern "C" void kernel_launch(void* const* d_in, const int* in_sizes, int n_in,
                              void* d_out, int out_size) {
    const float* feats = (const float*)d_in[0];
    const int* act = (const int*)d_in[1];
    const int* vid = (const int*)d_in[2];
    const float* proto = (const float*)d_in[3];
    float* out = (float*)d_out;

    cudaFuncSetAttribute(gemm_kernel, cudaFuncAttributeMaxDynamicSharedMemorySize,
                         SMEM_BYTES);

    prep_kernel<<<PREP_BLOCKS, 256>>>(vid);
    build_mask_kernel<<<BATCH * (TLEN / 64), 256>>>(act);
    gemm_kernel<<<dim3(NFULL + NQUART, 2), 512, SMEM_BYTES>>>(feats);
    finalize_kernel<<<(FIN_HALF + 255) / 256, 256>>>(
        (const float4*)proto, (float4*)out);
}

// round 15
// speedup vs baseline: 1.0942x; 1.0942x over previous
#include <cuda_runtime.h>
#include <cuda_bf16.h>
#include <cstdint>

// ---------------------------------------------------------------------------
// Shapes (fixed by the bench)
// ---------------------------------------------------------------------------
#define BATCH 16
#define TLEN  2048
#define CDIM  200
#define DDIM  2048
#define MPAD  256              // compacted class rows per batch (padded)

// GEMM tiling: swapped operands (A = feats, M = 128 dense d-rows; B = mask,
// N = nact classes). 16 warps as 4m x 4n, warp tile 32x32. Hybrid K tasks.
// Double-buffered KC=64 (R13-verified); convert-at-load (8 regs live, not 16).
#define KC      64             // k per smem chunk (64 bf16 = 128B SW128 row)
#define NTILE   128            // d rows per CTA (M)
#define NTASKS  256            // 16 dtiles x 16 batches
#define NFULL   148            // full-K tasks = exactly wave 1 (one per SM)
#define NQUART  ((NTASKS - NFULL) * 4)   // 432 quarter-K tasks
#define QCHUNKS 8              // chunks per quarter task (2048/64/4)

// smem: mask tile 2 x 16KB (128 rows x 128B), feats tile 2 x 16KB
#define SM_A0 0
#define SM_A1 16384
#define SM_B0 32768
#define SM_B1 (32768 + 16384)
#define SMEM_BYTES 65536

// ---------------------------------------------------------------------------
// Scratch — device symbols ONLY, never passed from host (ATS shadow trap!)
// ---------------------------------------------------------------------------
__device__ __align__(128) __nv_bfloat16 g_Amat[(size_t)BATCH * MPAD * TLEN]; // 16MB
__device__ float g_sums[MPAD * DDIM];   // indexed by TRUE class (0..199)
__device__ int   g_counts[MPAD];
__device__ int   g_clist[BATCH * MPAD]; // compact j -> true class c
__device__ int   g_cmap[BATCH * MPAD];  // true class c -> compact j (or -1)
__device__ int   g_nact[BATCH];

// ---------------------------------------------------------------------------
// helpers
// ---------------------------------------------------------------------------
__device__ __forceinline__ uint32_t smem_u32(const void* p) {
    uint32_t a;
    asm("{ .reg .u64 t; cvta.to.shared.u64 t, %1; cvt.u32.u64 %0, t; }"
        : "=r"(a) : "l"(p));
    return a;
}
__device__ __forceinline__ uint32_t sw128(uint32_t off) {
    return off ^ ((off >> 3) & 0x70);
}
__device__ __forceinline__ void sts128(uint32_t a, uint32_t x, uint32_t y,
                                       uint32_t z, uint32_t w) {
    asm volatile("st.shared.v4.b32 [%0], {%1,%2,%3,%4};"
                 :: "r"(a), "r"(x), "r"(y), "r"(z), "r"(w) : "memory");
}
__device__ __forceinline__ uint32_t pack_bf16x2(float lo, float hi) {
    uint32_t r;
    asm("cvt.rn.satfinite.bf16x2.f32 %0, %1, %2;" : "=r"(r) : "f"(hi), "f"(lo));
    return r;
}
__device__ __forceinline__ void cp_async16(uint32_t saddr, const void* gaddr) {
    asm volatile("cp.async.cg.shared.global [%0], [%1], 16;"
                 :: "r"(saddr), "l"(gaddr) : "memory");
}
__device__ __forceinline__ void cp_commit() {
    asm volatile("cp.async.commit_group;" ::: "memory");
}
__device__ __forceinline__ void cp_wait0() {
    asm volatile("cp.async.wait_group 0;" ::: "memory");
}
__device__ __forceinline__ void ldmatrix_x4(uint32_t* r, uint32_t addr) {
    asm volatile("ldmatrix.sync.aligned.m8n8.x4.shared.b16 {%0,%1,%2,%3}, [%4];"
                 : "=r"(r[0]), "=r"(r[1]), "=r"(r[2]), "=r"(r[3]) : "r"(addr));
}
__device__ __forceinline__ void mma16816(float* c, const uint32_t* a,
                                         uint32_t b0, uint32_t b1) {
    asm volatile(
        "mma.sync.aligned.m16n8k16.row.col.f32.bf16.bf16.f32 "
        "{%0,%1,%2,%3}, {%4,%5,%6,%7}, {%8,%9}, {%0,%1,%2,%3};"
        : "+f"(c[0]), "+f"(c[1]), "+f"(c[2]), "+f"(c[3])
        : "r"(a[0]), "r"(a[1]), "r"(a[2]), "r"(a[3]), "r"(b0), "r"(b1));
}

// ---------------------------------------------------------------------------
// Stage 0: blocks 0..15 per-batch class compaction; blocks 16+ zero sums +
// counts. The sums-zero here is load-bearing: it warms L2 with the g_sums
// lines right before the GEMM's atomics (removing it cost +42us in R10).
// ---------------------------------------------------------------------------
#define SUMS_U4 (MPAD * DDIM * 4 / 16)   // 131072
#define PREP_BLOCKS (BATCH + (SUMS_U4 + 255) / 256)
__global__ __launch_bounds__(256) void prep_kernel(const int* __restrict__ vid) {
    if (blockIdx.x >= BATCH) {
        int i = (blockIdx.x - BATCH) * 256 + threadIdx.x;
        const uint4 z = {0, 0, 0, 0};
        if (i < SUMS_U4) ((uint4*)g_sums)[i] = z;
        if (i < MPAD) g_counts[i] = 0;
        return;
    }
    __shared__ int warp_sums[8];
    __shared__ int warp_base[8];
    int b = blockIdx.x, tid = threadIdx.x;
    int lid = tid & 31, wid = tid >> 5;

    int flag = (tid < CDIM) ? (vid[b * CDIM + tid] != 0) : 0;
    uint32_t bal = __ballot_sync(0xFFFFFFFFu, flag);
    if (lid == 0) warp_sums[wid] = __popc(bal);
    __syncthreads();
    if (tid == 0) {
        int run = 0;
        for (int w = 0; w < 8; w++) { warp_base[w] = run; run += warp_sums[w]; }
        g_nact[b] = run;
    }
    __syncthreads();
    int j = warp_base[wid] + __popc(bal & ((1u << lid) - 1));
    if (flag) {
        g_cmap[b * MPAD + tid] = j;
        g_clist[b * MPAD + j] = tid;
    } else {
        g_cmap[b * MPAD + tid] = -1;
    }
}

// ---------------------------------------------------------------------------
// Stage 1: compacted bf16 mask Amat[b][j][t] + per-class counts.
// (verified-fast R9 version — unchanged)
// ---------------------------------------------------------------------------
__global__ __launch_bounds__(256) void build_mask_kernel(const int* __restrict__ act) {
    __shared__ __nv_bfloat16 m[CDIM][66];   // only rows < nact are written/read

    int tid = threadIdx.x;
    int b = blockIdx.x >> 5;
    int t0 = (blockIdx.x & 31) * 64;
    int nact = g_nact[b];
    int j = (tid < CDIM) ? g_cmap[b * MPAD + tid] : -1;

    const __nv_bfloat16 one = __float2bfloat16(1.0f);
    const __nv_bfloat16 zero = __float2bfloat16(0.0f);

    const int* ap = act + ((size_t)b * TLEN + t0) * CDIM + tid;
    int cnt = 0;
    if (j >= 0) {
#pragma unroll 1
        for (int p = 0; p < 8; p++) {
            int vr[8];
#pragma unroll
            for (int u = 0; u < 8; u++)          // 8 coalesced loads in flight
                vr[u] = ap[(size_t)(p * 8 + u) * CDIM];
#pragma unroll
            for (int u = 0; u < 8; u++) {
                bool on = vr[u] != 0;
                m[j][p * 8 + u] = on ? one : zero;
                cnt += on;
            }
        }
        if (cnt) atomicAdd(&g_counts[tid], cnt);
    }
    __syncthreads();

    int lid = tid & 31, wid = tid >> 5;
    for (int jj = wid; jj < nact; jj += 8) {
        uint32_t v = *(const uint32_t*)&m[jj][2 * lid];
        *(uint32_t*)((char*)g_Amat +
                     ((size_t)(b * MPAD + jj) * TLEN + t0 + 2 * lid) * 2) = v;
    }
}

// ---------------------------------------------------------------------------
// Static-NT compute body (warp tile m32 x n32): per ks, 2 A ldsm + NB B ldsm
// + 2*NT mma. NT compile-time -> clean static scheduling.
// ---------------------------------------------------------------------------
template <int NT>
__device__ __forceinline__ void compute_t(uint32_t mask_base, uint32_t feat_base,
                                          const uint32_t* a_off,
                                          const uint32_t* b_off,
                                          float acc[2][4][4]) {
    constexpr int NB = (NT + 1) >> 1;
#pragma unroll
    for (int ks = 0; ks < 4; ks++) {
        uint32_t a[2][4], bf[NB][4];
#pragma unroll
        for (int mt = 0; mt < 2; mt++)
            ldmatrix_x4(a[mt], feat_base + sw128(a_off[mt] + ks * 32));
#pragma unroll
        for (int nb = 0; nb < NB; nb++)
            ldmatrix_x4(bf[nb], mask_base + sw128(b_off[nb] + ks * 32));
#pragma unroll
        for (int mt = 0; mt < 2; mt++)
#pragma unroll
            for (int nt = 0; nt < NT; nt++)
                mma16816(acc[mt][nt], a[mt],
                         bf[nt >> 1][(nt & 1) * 2], bf[nt >> 1][(nt & 1) * 2 + 1]);
    }
}

// ---------------------------------------------------------------------------
// Stage 2: per-batch bf16 GEMM (R13 structure verbatim; only change: feats
// are converted f32->bf16 inside issue_loads so just 8 packed regs stay live
// across compute instead of 16 floats, and cvt leaves the barrier tail).
// ---------------------------------------------------------------------------
__global__ __launch_bounds__(512, 1) void gemm_kernel(const float* __restrict__ feats) {
    int task, ck0, nch;
    if (blockIdx.x < NFULL) {
        task = blockIdx.x;           ck0 = 0;                 nch = 32;
    } else {
        int r = blockIdx.x - NFULL;
        task = NFULL + (r >> 2);     ck0 = (r & 3) * QCHUNKS; nch = QCHUNKS;
    }
    const int b = task & 15;
    const int d0 = (task >> 4) * NTILE;
    const int nbase = blockIdx.y * 128;     // class window base (2nd CTA rare)
    const int nact = g_nact[b];
    if (nbase >= nact) return;
    const int nlim = nact - nbase;          // classes in this CTA's window

    extern __shared__ char smem[];
    const uint32_t sb = smem_u32(smem);
    const int tid = threadIdx.x;
    const int lane = tid & 31, wid = tid >> 5;
    const int wm = wid & 3;             // m: d rows wm*32 (dense) — SMSP id
    const int wn = wid >> 2;            // n: class cols wn*32

    const int nrem = nlim - wn * 32;
    const int ncap = nrem < 32 ? (nrem > 0 ? nrem : 0) : 32;
    const int ntmax = (ncap + 7) >> 3;          // 0..4

    const int dcol = tid & 127;
    const int kq = tid >> 7;            // 0..3 -> k = kq*16 .. +15

    float acc[2][4][4];
#pragma unroll
    for (int mt = 0; mt < 2; mt++)
#pragma unroll
        for (int i = 0; i < 4; i++)
#pragma unroll
            for (int r = 0; r < 4; r++) acc[mt][i][r] = 0.0f;

    uint32_t a_off[2];
#pragma unroll
    for (int mt = 0; mt < 2; mt++) {
        int rowA = wm * 32 + mt * 16 + (lane & 15);
        a_off[mt] = (uint32_t)(rowA * 128 + (lane >> 4) * 16);
    }
    uint32_t b_off[2];
#pragma unroll
    for (int nb = 0; nb < 2; nb++) {
        int rowB = wn * 32 + nb * 16 + ((lane >> 4) << 3) + (lane & 7);
        b_off[nb] = (uint32_t)(rowB * 128 + ((lane >> 3) & 1) * 16);
    }

    const __nv_bfloat16* abase_g = g_Amat + (size_t)(b * MPAD + nbase) * TLEN;
    const float* fbase = feats + (size_t)b * TLEN * DDIM;

    uint32_t pb[8];   // converted feats (bf16x2) — only 8 regs live

    auto issue_loads = [&](int ck, int s) {
        const int k0 = ck * KC;
        const uint32_t abase = sb + (s ? SM_A1 : SM_A0);
#pragma unroll
        for (int it = 0; it < 2; it++) {
            int idx = it * 512 + tid;
            int row = idx >> 3, seg = idx & 7;
            if (row < nlim) {  // class rows; garbage never consumed
                const void* g = abase_g + (size_t)row * TLEN + k0 + seg * 8;
                cp_async16(abase + sw128((uint32_t)(row * 128 + seg * 16)), g);
            }
        }
        cp_commit();
        const float* fp = fbase + (size_t)(k0 + kq * 16) * DDIM + d0 + dcol;
        float f[16];
#pragma unroll
        for (int jj = 0; jj < 16; jj++) f[jj] = fp[(size_t)jj * DDIM];
#pragma unroll
        for (int jj = 0; jj < 8; jj++)
            pb[jj] = pack_bf16x2(f[2 * jj], f[2 * jj + 1]);
    };
    auto store_b = [&](int s) {
        const uint32_t bbase = sb + (s ? SM_B1 : SM_B0);
        uint32_t o0 = (uint32_t)(dcol * 128 + kq * 32);
        sts128(bbase + sw128(o0), pb[0], pb[1], pb[2], pb[3]);
        sts128(bbase + sw128(o0 + 16), pb[4], pb[5], pb[6], pb[7]);
    };
    auto compute = [&](int s) {
        const uint32_t mask_base = sb + (s ? SM_A1 : SM_A0);
        const uint32_t feat_base = sb + (s ? SM_B1 : SM_B0);
        switch (ntmax) {
            case 4: compute_t<4>(mask_base, feat_base, a_off, b_off, acc); break;
            case 3: compute_t<3>(mask_base, feat_base, a_off, b_off, acc); break;
            case 2: compute_t<2>(mask_base, feat_base, a_off, b_off, acc); break;
            case 1: compute_t<1>(mask_base, feat_base, a_off, b_off, acc); break;
            default: break;
        }
    };

    issue_loads(ck0, 0);
    cp_wait0();
    store_b(0);
    __syncthreads();

#pragma unroll 1
    for (int i = 0; i < nch; i++) {
        const int s = i & 1;
        if (i + 1 < nch) issue_loads(ck0 + i + 1, s ^ 1);
        compute(s);
        if (i + 1 < nch) {
            store_b(s ^ 1);
            cp_wait0();
            __syncthreads();
        }
    }

    // epilogue: fragment rows = d (dense), cols = compact classes -> scatter
    {
        const int col2 = (lane & 3) * 2;
        const int* clist = g_clist + b * MPAD;
#pragma unroll
        for (int mt = 0; mt < 2; mt++) {
            const int dd = d0 + wm * 32 + mt * 16 + (lane >> 2);
#pragma unroll
            for (int nt = 0; nt < 4; nt++) {
                if (nt >= ntmax) break;
                int jn = nbase + wn * 32 + nt * 8 + col2;
                int c0 = (jn < nact) ? clist[jn] : -1;
                int c1 = (jn + 1 < nact) ? clist[jn + 1] : -1;
                if (c0 >= 0) {
                    float* gp = g_sums + (size_t)c0 * DDIM + dd;
                    atomicAdd(gp, acc[mt][nt][0]);
                    atomicAdd(gp + 8, acc[mt][nt][2]);
                }
                if (c1 >= 0) {
                    float* gp = g_sums + (size_t)c1 * DDIM + dd;
                    atomicAdd(gp, acc[mt][nt][1]);
                    atomicAdd(gp + 8, acc[mt][nt][3]);
                }
            }
        }
    }
}

// ---------------------------------------------------------------------------
// Stage 3: momentum update — 2 independent float4 chains per thread (ILP)
// ---------------------------------------------------------------------------
#define FIN_HALF (CDIM * DDIM / 4 / 2)   // 51200
__global__ void finalize_kernel(const float4* __restrict__ proto,
                                float4* __restrict__ out) {
    int i = blockIdx.x * 256 + threadIdx.x;
    if (i >= FIN_HALF) return;
    int i2 = i + FIN_HALF;
    int ca = i >> 9, cb = i2 >> 9;
    float4 pa = proto[i], pb = proto[i2];
    float4 sa = ((const float4*)g_sums)[i], sb = ((const float4*)g_sums)[i2];
    int na = g_counts[ca], nb = g_counts[cb];
    float ia = 0.001f / fmaxf((float)na, 1.0f);
    float ib = 0.001f / fmaxf((float)nb, 1.0f);
    float4 ra, rb;
    ra.x = 0.999f * pa.x + sa.x * ia;  ra.y = 0.999f * pa.y + sa.y * ia;
    ra.z = 0.999f * pa.z + sa.z * ia;  ra.w = 0.999f * pa.w + sa.w * ia;
    rb.x = 0.999f * pb.x + sb.x * ib;  rb.y = 0.999f * pb.y + sb.y * ib;
    rb.z = 0.999f * pb.z + sb.z * ib;  rb.w = 0.999f * pb.w + sb.w * ib;
    out[i]  = (na > 0) ? ra : pa;
    out[i2] = (nb > 0) ? rb : pb;
}

// ---------------------------------------------------------------------------
// Launch
// ---------------------------------------------------------------------------
extern "C" void kernel_launch(void* const* d_in, const int* in_sizes, int n_in,
                              void* d_out, int out_size) {
    const float* feats = (const float*)d_in[0];
    const int* act = (const int*)d_in[1];
    const int* vid = (const int*)d_in[2];
    const float* proto = (const float*)d_in[3];
    float* out = (float*)d_out;

    cudaFuncSetAttribute(gemm_kernel, cudaFuncAttributeMaxDynamicSharedMemorySize,
                         SMEM_BYTES);

    prep_kernel<<<PREP_BLOCKS, 256>>>(vid);
    build_mask_kernel<<<BATCH * (TLEN / 64), 256>>>(act);
    gemm_kernel<<<dim3(NFULL + NQUART, 2), 512, SMEM_BYTES>>>(feats);
    finalize_kernel<<<(FIN_HALF + 255) / 256, 256>>>(
        (const float4*)proto, (float4*)out);
}

// round 16
// speedup vs baseline: 1.4030x; 1.2821x over previous
#include <cuda_runtime.h>
#include <cuda_bf16.h>
#include <cstdint>

// ---------------------------------------------------------------------------
// Shapes (fixed by the bench)
// ---------------------------------------------------------------------------
#define BATCH 16
#define TLEN  2048
#define CDIM  200
#define DDIM  2048
#define MPAD  256              // compacted class rows per batch (padded)

// GEMM tiling: swapped operands (A = feats, M = 128 dense d-rows; B = mask,
// N = nact classes). 16 warps as 4m x 4n, warp tile 32x32. Hybrid K tasks.
// Double-buffered KC=64 (R13-verified) with software-pipelined store_b:
// the cvt+STS for chunk i+1 runs BEFORE compute(i) (its stage was drained by
// the i-1 barrier), consuming feats LDG'd one iteration earlier.
#define KC      64             // k per smem chunk (64 bf16 = 128B SW128 row)
#define NTILE   128            // d rows per CTA (M)
#define NTASKS  256            // 16 dtiles x 16 batches
#define NFULL   148            // full-K tasks = exactly wave 1 (one per SM)
#define NQUART  ((NTASKS - NFULL) * 4)   // 432 quarter-K tasks
#define QCHUNKS 8              // chunks per quarter task (2048/64/4)

// smem: mask tile 2 x 16KB (128 rows x 128B), feats tile 2 x 16KB
#define SM_A0 0
#define SM_A1 16384
#define SM_B0 32768
#define SM_B1 (32768 + 16384)
#define SMEM_BYTES 65536

// ---------------------------------------------------------------------------
// Scratch — device symbols ONLY, never passed from host (ATS shadow trap!)
// ---------------------------------------------------------------------------
__device__ __align__(128) __nv_bfloat16 g_Amat[(size_t)BATCH * MPAD * TLEN]; // 16MB
__device__ float g_sums[MPAD * DDIM];   // indexed by TRUE class (0..199)
__device__ int   g_counts[MPAD];
__device__ int   g_clist[BATCH * MPAD]; // compact j -> true class c
__device__ int   g_cmap[BATCH * MPAD];  // true class c -> compact j (or -1)
__device__ int   g_nact[BATCH];

// ---------------------------------------------------------------------------
// helpers
// ---------------------------------------------------------------------------
__device__ __forceinline__ uint32_t smem_u32(const void* p) {
    uint32_t a;
    asm("{ .reg .u64 t; cvta.to.shared.u64 t, %1; cvt.u32.u64 %0, t; }"
        : "=r"(a) : "l"(p));
    return a;
}
__device__ __forceinline__ uint32_t sw128(uint32_t off) {
    return off ^ ((off >> 3) & 0x70);
}
__device__ __forceinline__ void sts128(uint32_t a, uint32_t x, uint32_t y,
                                       uint32_t z, uint32_t w) {
    asm volatile("st.shared.v4.b32 [%0], {%1,%2,%3,%4};"
                 :: "r"(a), "r"(x), "r"(y), "r"(z), "r"(w) : "memory");
}
__device__ __forceinline__ uint32_t pack_bf16x2(float lo, float hi) {
    uint32_t r;
    asm("cvt.rn.satfinite.bf16x2.f32 %0, %1, %2;" : "=r"(r) : "f"(hi), "f"(lo));
    return r;
}
__device__ __forceinline__ void cp_async16(uint32_t saddr, const void* gaddr) {
    asm volatile("cp.async.cg.shared.global [%0], [%1], 16;"
                 :: "r"(saddr), "l"(gaddr) : "memory");
}
__device__ __forceinline__ void cp_commit() {
    asm volatile("cp.async.commit_group;" ::: "memory");
}
__device__ __forceinline__ void cp_wait0() {
    asm volatile("cp.async.wait_group 0;" ::: "memory");
}
__device__ __forceinline__ void ldmatrix_x4(uint32_t* r, uint32_t addr) {
    asm volatile("ldmatrix.sync.aligned.m8n8.x4.shared.b16 {%0,%1,%2,%3}, [%4];"
                 : "=r"(r[0]), "=r"(r[1]), "=r"(r[2]), "=r"(r[3]) : "r"(addr));
}
__device__ __forceinline__ void mma16816(float* c, const uint32_t* a,
                                         uint32_t b0, uint32_t b1) {
    asm volatile(
        "mma.sync.aligned.m16n8k16.row.col.f32.bf16.bf16.f32 "
        "{%0,%1,%2,%3}, {%4,%5,%6,%7}, {%8,%9}, {%0,%1,%2,%3};"
        : "+f"(c[0]), "+f"(c[1]), "+f"(c[2]), "+f"(c[3])
        : "r"(a[0]), "r"(a[1]), "r"(a[2]), "r"(a[3]), "r"(b0), "r"(b1));
}

// ---------------------------------------------------------------------------
// Stage 0: blocks 0..15 per-batch class compaction; blocks 16+ zero sums +
// counts. The sums-zero here is load-bearing: it warms L2 with the g_sums
// lines right before the GEMM's atomics (removing it cost +42us in R10).
// ---------------------------------------------------------------------------
#define SUMS_U4 (MPAD * DDIM * 4 / 16)   // 131072
#define PREP_BLOCKS (BATCH + (SUMS_U4 + 255) / 256)
__global__ __launch_bounds__(256) void prep_kernel(const int* __restrict__ vid) {
    if (blockIdx.x >= BATCH) {
        int i = (blockIdx.x - BATCH) * 256 + threadIdx.x;
        const uint4 z = {0, 0, 0, 0};
        if (i < SUMS_U4) ((uint4*)g_sums)[i] = z;
        if (i < MPAD) g_counts[i] = 0;
        return;
    }
    __shared__ int warp_sums[8];
    __shared__ int warp_base[8];
    int b = blockIdx.x, tid = threadIdx.x;
    int lid = tid & 31, wid = tid >> 5;

    int flag = (tid < CDIM) ? (vid[b * CDIM + tid] != 0) : 0;
    uint32_t bal = __ballot_sync(0xFFFFFFFFu, flag);
    if (lid == 0) warp_sums[wid] = __popc(bal);
    __syncthreads();
    if (tid == 0) {
        int run = 0;
        for (int w = 0; w < 8; w++) { warp_base[w] = run; run += warp_sums[w]; }
        g_nact[b] = run;
    }
    __syncthreads();
    int j = warp_base[wid] + __popc(bal & ((1u << lid) - 1));
    if (flag) {
        g_cmap[b * MPAD + tid] = j;
        g_clist[b * MPAD + j] = tid;
    } else {
        g_cmap[b * MPAD + tid] = -1;
    }
}

// ---------------------------------------------------------------------------
// Stage 1: compacted bf16 mask Amat[b][j][t] + per-class counts.
// (verified-fast R9 version — unchanged)
// ---------------------------------------------------------------------------
__global__ __launch_bounds__(256) void build_mask_kernel(const int* __restrict__ act) {
    __shared__ __nv_bfloat16 m[CDIM][66];   // only rows < nact are written/read

    int tid = threadIdx.x;
    int b = blockIdx.x >> 5;
    int t0 = (blockIdx.x & 31) * 64;
    int nact = g_nact[b];
    int j = (tid < CDIM) ? g_cmap[b * MPAD + tid] : -1;

    const __nv_bfloat16 one = __float2bfloat16(1.0f);
    const __nv_bfloat16 zero = __float2bfloat16(0.0f);

    const int* ap = act + ((size_t)b * TLEN + t0) * CDIM + tid;
    int cnt = 0;
    if (j >= 0) {
#pragma unroll 1
        for (int p = 0; p < 8; p++) {
            int vr[8];
#pragma unroll
            for (int u = 0; u < 8; u++)          // 8 coalesced loads in flight
                vr[u] = ap[(size_t)(p * 8 + u) * CDIM];
#pragma unroll
            for (int u = 0; u < 8; u++) {
                bool on = vr[u] != 0;
                m[j][p * 8 + u] = on ? one : zero;
                cnt += on;
            }
        }
        if (cnt) atomicAdd(&g_counts[tid], cnt);
    }
    __syncthreads();

    int lid = tid & 31, wid = tid >> 5;
    for (int jj = wid; jj < nact; jj += 8) {
        uint32_t v = *(const uint32_t*)&m[jj][2 * lid];
        *(uint32_t*)((char*)g_Amat +
                     ((size_t)(b * MPAD + jj) * TLEN + t0 + 2 * lid) * 2) = v;
    }
}

// ---------------------------------------------------------------------------
// Static-NT compute body (warp tile m32 x n32): per ks, 2 A ldsm + NB B ldsm
// + 2*NT mma. NT compile-time -> clean static scheduling.
// ---------------------------------------------------------------------------
template <int NT>
__device__ __forceinline__ void compute_t(uint32_t mask_base, uint32_t feat_base,
                                          const uint32_t* a_off,
                                          const uint32_t* b_off,
                                          float acc[2][4][4]) {
    constexpr int NB = (NT + 1) >> 1;
#pragma unroll
    for (int ks = 0; ks < 4; ks++) {
        uint32_t a[2][4], bf[NB][4];
#pragma unroll
        for (int mt = 0; mt < 2; mt++)
            ldmatrix_x4(a[mt], feat_base + sw128(a_off[mt] + ks * 32));
#pragma unroll
        for (int nb = 0; nb < NB; nb++)
            ldmatrix_x4(bf[nb], mask_base + sw128(b_off[nb] + ks * 32));
#pragma unroll
        for (int mt = 0; mt < 2; mt++)
#pragma unroll
            for (int nt = 0; nt < NT; nt++)
                mma16816(acc[mt][nt], a[mt],
                         bf[nt >> 1][(nt & 1) * 2], bf[nt >> 1][(nt & 1) * 2 + 1]);
    }
}

// ---------------------------------------------------------------------------
// Stage 2: per-batch bf16 GEMM — R13 structure with the store_b moved ahead
// of compute (stage drained by the previous barrier) and feats LDG moved one
// iteration earlier so store_b never stalls on fresh loads. Live register
// set identical to R13 (single fst[16], cvt stays in store_b).
// ---------------------------------------------------------------------------
__global__ __launch_bounds__(512, 1) void gemm_kernel(const float* __restrict__ feats) {
    int task, ck0, nch;
    if (blockIdx.x < NFULL) {
        task = blockIdx.x;           ck0 = 0;                 nch = 32;
    } else {
        int r = blockIdx.x - NFULL;
        task = NFULL + (r >> 2);     ck0 = (r & 3) * QCHUNKS; nch = QCHUNKS;
    }
    const int b = task & 15;
    const int d0 = (task >> 4) * NTILE;
    const int nbase = blockIdx.y * 128;     // class window base (2nd CTA rare)
    const int nact = g_nact[b];
    if (nbase >= nact) return;
    const int nlim = nact - nbase;          // classes in this CTA's window

    extern __shared__ char smem[];
    const uint32_t sb = smem_u32(smem);
    const int tid = threadIdx.x;
    const int lane = tid & 31, wid = tid >> 5;
    const int wm = wid & 3;             // m: d rows wm*32 (dense) — SMSP id
    const int wn = wid >> 2;            // n: class cols wn*32

    const int nrem = nlim - wn * 32;
    const int ncap = nrem < 32 ? (nrem > 0 ? nrem : 0) : 32;
    const int ntmax = (ncap + 7) >> 3;          // 0..4

    const int dcol = tid & 127;
    const int kq = tid >> 7;            // 0..3 -> k = kq*16 .. +15

    float acc[2][4][4];
#pragma unroll
    for (int mt = 0; mt < 2; mt++)
#pragma unroll
        for (int i = 0; i < 4; i++)
#pragma unroll
            for (int r = 0; r < 4; r++) acc[mt][i][r] = 0.0f;

    uint32_t a_off[2];
#pragma unroll
    for (int mt = 0; mt < 2; mt++) {
        int rowA = wm * 32 + mt * 16 + (lane & 15);
        a_off[mt] = (uint32_t)(rowA * 128 + (lane >> 4) * 16);
    }
    uint32_t b_off[2];
#pragma unroll
    for (int nb = 0; nb < 2; nb++) {
        int rowB = wn * 32 + nb * 16 + ((lane >> 4) << 3) + (lane & 7);
        b_off[nb] = (uint32_t)(rowB * 128 + ((lane >> 3) & 1) * 16);
    }

    const __nv_bfloat16* abase_g = g_Amat + (size_t)(b * MPAD + nbase) * TLEN;
    const float* fbase = feats + (size_t)b * TLEN * DDIM;

    float fst[16];   // feats staging (loaded 1 iter ahead of its store_b)

    auto cpA = [&](int ck, int s) {      // mask tile -> stage s (+ commit)
        const int k0 = ck * KC;
        const uint32_t abase = sb + (s ? SM_A1 : SM_A0);
#pragma unroll
        for (int it = 0; it < 2; it++) {
            int idx = it * 512 + tid;
            int row = idx >> 3, seg = idx & 7;
            if (row < nlim) {  // class rows; garbage never consumed
                const void* g = abase_g + (size_t)row * TLEN + k0 + seg * 8;
                cp_async16(abase + sw128((uint32_t)(row * 128 + seg * 16)), g);
            }
        }
        cp_commit();
    };
    auto ldg_fst = [&](int ck) {         // feats LDG -> fst (in flight)
        const float* fp = fbase + (size_t)(ck * KC + kq * 16) * DDIM + d0 + dcol;
#pragma unroll
        for (int jj = 0; jj < 16; jj++) fst[jj] = fp[(size_t)jj * DDIM];
    };
    auto store_b = [&](int s) {          // cvt fst -> STS into stage s
        const uint32_t bbase = sb + (s ? SM_B1 : SM_B0);
        uint32_t p[8];
#pragma unroll
        for (int jj = 0; jj < 8; jj++)
            p[jj] = pack_bf16x2(fst[2 * jj], fst[2 * jj + 1]);
        uint32_t o0 = (uint32_t)(dcol * 128 + kq * 32);
        sts128(bbase + sw128(o0), p[0], p[1], p[2], p[3]);
        sts128(bbase + sw128(o0 + 16), p[4], p[5], p[6], p[7]);
    };
    auto compute = [&](int s) {
        const uint32_t mask_base = sb + (s ? SM_A1 : SM_A0);
        const uint32_t feat_base = sb + (s ? SM_B1 : SM_B0);
        switch (ntmax) {
            case 4: compute_t<4>(mask_base, feat_base, a_off, b_off, acc); break;
            case 3: compute_t<3>(mask_base, feat_base, a_off, b_off, acc); break;
            case 2: compute_t<2>(mask_base, feat_base, a_off, b_off, acc); break;
            case 1: compute_t<1>(mask_base, feat_base, a_off, b_off, acc); break;
            default: break;
        }
    };

    // prologue: chunk0 staged (one-time stall on fst(0)); fst(1) in flight
    ldg_fst(ck0);
    cpA(ck0, 0);
    store_b(0);                 // stalls on fst(ck0) loads — once per CTA
    if (nch > 1) ldg_fst(ck0 + 1);
    cp_wait0();                 // A(chunk0) complete
    __syncthreads();

#pragma unroll 1
    for (int i = 0; i < nch; i++) {
        const int s = i & 1;
        if (i + 1 < nch) {
            store_b(s ^ 1);              // B(i+1): fst loaded at iter i-1
            cpA(ck0 + i + 1, s ^ 1);     // A(i+1): lands during compute
            if (i + 2 < nch) ldg_fst(ck0 + i + 2);  // feats(i+2) in flight
        }
        compute(s);
        if (i + 1 < nch) {
            cp_wait0();
            __syncthreads();
        }
    }

    // epilogue: fragment rows = d (dense), cols = compact classes -> scatter
    {
        const int col2 = (lane & 3) * 2;
        const int* clist = g_clist + b * MPAD;
#pragma unroll
        for (int mt = 0; mt < 2; mt++) {
            const int dd = d0 + wm * 32 + mt * 16 + (lane >> 2);
#pragma unroll
            for (int nt = 0; nt < 4; nt++) {
                if (nt >= ntmax) break;
                int jn = nbase + wn * 32 + nt * 8 + col2;
                int c0 = (jn < nact) ? clist[jn] : -1;
                int c1 = (jn + 1 < nact) ? clist[jn + 1] : -1;
                if (c0 >= 0) {
                    float* gp = g_sums + (size_t)c0 * DDIM + dd;
                    atomicAdd(gp, acc[mt][nt][0]);
                    atomicAdd(gp + 8, acc[mt][nt][2]);
                }
                if (c1 >= 0) {
                    float* gp = g_sums + (size_t)c1 * DDIM + dd;
                    atomicAdd(gp, acc[mt][nt][1]);
                    atomicAdd(gp + 8, acc[mt][nt][3]);
                }
            }
        }
    }
}

// ---------------------------------------------------------------------------
// Stage 3: momentum update — 2 independent float4 chains per thread (ILP)
// ---------------------------------------------------------------------------
#define FIN_HALF (CDIM * DDIM / 4 / 2)   // 51200
__global__ void finalize_kernel(const float4* __restrict__ proto,
                                float4* __restrict__ out) {
    int i = blockIdx.x * 256 + threadIdx.x;
    if (i >= FIN_HALF) return;
    int i2 = i + FIN_HALF;
    int ca = i >> 9, cb = i2 >> 9;
    float4 pa = proto[i], pb = proto[i2];
    float4 sa = ((const float4*)g_sums)[i], sb = ((const float4*)g_sums)[i2];
    int na = g_counts[ca], nb = g_counts[cb];
    float ia = 0.001f / fmaxf((float)na, 1.0f);
    float ib = 0.001f / fmaxf((float)nb, 1.0f);
    float4 ra, rb;
    ra.x = 0.999f * pa.x + sa.x * ia;  ra.y = 0.999f * pa.y + sa.y * ia;
    ra.z = 0.999f * pa.z + sa.z * ia;  ra.w = 0.999f * pa.w + sa.w * ia;
    rb.x = 0.999f * pb.x + sb.x * ib;  rb.y = 0.999f * pb.y + sb.y * ib;
    rb.z = 0.999f * pb.z + sb.z * ib;  rb.w = 0.999f * pb.w + sb.w * ib;
    out[i]  = (na > 0) ? ra : pa;
    out[i2] = (nb > 0) ? rb : pb;
}

// ---------------------------------------------------------------------------
// Launch
// ---------------------------------------------------------------------------
extern "C" void kernel_launch(void* const* d_in, const int* in_sizes, int n_in,
                              void* d_out, int out_size) {
    const float* feats = (const float*)d_in[0];
    const int* act = (const int*)d_in[1];
    const int* vid = (const int*)d_in[2];
    const float* proto = (const float*)d_in[3];
    float* out = (float*)d_out;

    cudaFuncSetAttribute(gemm_kernel, cudaFuncAttributeMaxDynamicSharedMemorySize,
                         SMEM_BYTES);

    prep_kernel<<<PREP_BLOCKS, 256>>>(vid);
    build_mask_kernel<<<BATCH * (TLEN / 64), 256>>>(act);
    gemm_kernel<<<dim3(NFULL + NQUART, 2), 512, SMEM_BYTES>>>(feats);
    finalize_kernel<<<(FIN_HALF + 255) / 256, 256>>>(
        (const float4*)proto, (float4*)out);
}

// round 17
// speedup vs baseline: 1.4395x; 1.0260x over previous
#include <cuda_runtime.h>
#include <cuda_bf16.h>
#include <cstdint>

// ---------------------------------------------------------------------------
// Shapes (fixed by the bench)
// ---------------------------------------------------------------------------
#define BATCH 16
#define TLEN  2048
#define CDIM  200
#define DDIM  2048
#define MPAD  256              // compacted class rows per batch (padded)

// GEMM tiling: swapped operands (A = feats, M = 128 dense d-rows; B = mask,
// N = nact classes). 16 warps as 4m x 4n, warp tile 32x32. Hybrid K tasks.
// R16 pipeline doubled: each double-buffer stage holds TWO 16KB k-subtiles
// per operand -> half the barriers (the measured ~500cyc/chunk overhead).
#define KC      64             // k per smem sub-chunk (64 bf16 = 128B SW128 row)
#define NTILE   128            // d rows per CTA (M)
#define NTASKS  256            // 16 dtiles x 16 batches
#define NFULL   148            // full-K tasks = exactly wave 1 (one per SM)
#define NQUART  ((NTASKS - NFULL) * 4)   // 432 quarter-K tasks
#define QCHUNKS 8              // sub-chunks per quarter task

// smem: 2 stages x (32KB mask + 32KB feats) = 128KB; sub s at +sub*16384
#define SM_MASK(st) ((st) * 32768)
#define SM_FEAT(st) (65536 + (st) * 32768)
#define SMEM_BYTES 131072

// ---------------------------------------------------------------------------
// Scratch — device symbols ONLY, never passed from host (ATS shadow trap!)
// ---------------------------------------------------------------------------
__device__ __align__(128) __nv_bfloat16 g_Amat[(size_t)BATCH * MPAD * TLEN]; // 16MB
__device__ float g_sums[MPAD * DDIM];   // indexed by TRUE class (0..199)
__device__ int   g_counts[MPAD];
__device__ int   g_clist[BATCH * MPAD]; // compact j -> true class c
__device__ int   g_cmap[BATCH * MPAD];  // true class c -> compact j (or -1)
__device__ int   g_nact[BATCH];

// ---------------------------------------------------------------------------
// helpers
// ---------------------------------------------------------------------------
__device__ __forceinline__ uint32_t smem_u32(const void* p) {
    uint32_t a;
    asm("{ .reg .u64 t; cvta.to.shared.u64 t, %1; cvt.u32.u64 %0, t; }"
        : "=r"(a) : "l"(p));
    return a;
}
__device__ __forceinline__ uint32_t sw128(uint32_t off) {
    return off ^ ((off >> 3) & 0x70);
}
__device__ __forceinline__ void sts128(uint32_t a, uint32_t x, uint32_t y,
                                       uint32_t z, uint32_t w) {
    asm volatile("st.shared.v4.b32 [%0], {%1,%2,%3,%4};"
                 :: "r"(a), "r"(x), "r"(y), "r"(z), "r"(w) : "memory");
}
__device__ __forceinline__ uint32_t pack_bf16x2(float lo, float hi) {
    uint32_t r;
    asm("cvt.rn.satfinite.bf16x2.f32 %0, %1, %2;" : "=r"(r) : "f"(hi), "f"(lo));
    return r;
}
__device__ __forceinline__ void cp_async16(uint32_t saddr, const void* gaddr) {
    asm volatile("cp.async.cg.shared.global [%0], [%1], 16;"
                 :: "r"(saddr), "l"(gaddr) : "memory");
}
__device__ __forceinline__ void cp_commit() {
    asm volatile("cp.async.commit_group;" ::: "memory");
}
__device__ __forceinline__ void cp_wait0() {
    asm volatile("cp.async.wait_group 0;" ::: "memory");
}
__device__ __forceinline__ void ldmatrix_x4(uint32_t* r, uint32_t addr) {
    asm volatile("ldmatrix.sync.aligned.m8n8.x4.shared.b16 {%0,%1,%2,%3}, [%4];"
                 : "=r"(r[0]), "=r"(r[1]), "=r"(r[2]), "=r"(r[3]) : "r"(addr));
}
__device__ __forceinline__ void mma16816(float* c, const uint32_t* a,
                                         uint32_t b0, uint32_t b1) {
    asm volatile(
        "mma.sync.aligned.m16n8k16.row.col.f32.bf16.bf16.f32 "
        "{%0,%1,%2,%3}, {%4,%5,%6,%7}, {%8,%9}, {%0,%1,%2,%3};"
        : "+f"(c[0]), "+f"(c[1]), "+f"(c[2]), "+f"(c[3])
        : "r"(a[0]), "r"(a[1]), "r"(a[2]), "r"(a[3]), "r"(b0), "r"(b1));
}

// ---------------------------------------------------------------------------
// Stage 0: blocks 0..15 per-batch class compaction; blocks 16+ zero sums +
// counts. The sums-zero here is load-bearing: it warms L2 with the g_sums
// lines right before the GEMM's atomics (removing it cost +42us in R10).
// ---------------------------------------------------------------------------
#define SUMS_U4 (MPAD * DDIM * 4 / 16)   // 131072
#define PREP_BLOCKS (BATCH + (SUMS_U4 + 255) / 256)
__global__ __launch_bounds__(256) void prep_kernel(const int* __restrict__ vid) {
    if (blockIdx.x >= BATCH) {
        int i = (blockIdx.x - BATCH) * 256 + threadIdx.x;
        const uint4 z = {0, 0, 0, 0};
        if (i < SUMS_U4) ((uint4*)g_sums)[i] = z;
        if (i < MPAD) g_counts[i] = 0;
        return;
    }
    __shared__ int warp_sums[8];
    __shared__ int warp_base[8];
    int b = blockIdx.x, tid = threadIdx.x;
    int lid = tid & 31, wid = tid >> 5;

    int flag = (tid < CDIM) ? (vid[b * CDIM + tid] != 0) : 0;
    uint32_t bal = __ballot_sync(0xFFFFFFFFu, flag);
    if (lid == 0) warp_sums[wid] = __popc(bal);
    __syncthreads();
    if (tid == 0) {
        int run = 0;
        for (int w = 0; w < 8; w++) { warp_base[w] = run; run += warp_sums[w]; }
        g_nact[b] = run;
    }
    __syncthreads();
    int j = warp_base[wid] + __popc(bal & ((1u << lid) - 1));
    if (flag) {
        g_cmap[b * MPAD + tid] = j;
        g_clist[b * MPAD + j] = tid;
    } else {
        g_cmap[b * MPAD + tid] = -1;
    }
}

// ---------------------------------------------------------------------------
// Stage 1: compacted bf16 mask Amat[b][j][t] + per-class counts.
// (verified-fast R9 version — unchanged)
// ---------------------------------------------------------------------------
__global__ __launch_bounds__(256) void build_mask_kernel(const int* __restrict__ act) {
    __shared__ __nv_bfloat16 m[CDIM][66];   // only rows < nact are written/read

    int tid = threadIdx.x;
    int b = blockIdx.x >> 5;
    int t0 = (blockIdx.x & 31) * 64;
    int nact = g_nact[b];
    int j = (tid < CDIM) ? g_cmap[b * MPAD + tid] : -1;

    const __nv_bfloat16 one = __float2bfloat16(1.0f);
    const __nv_bfloat16 zero = __float2bfloat16(0.0f);

    const int* ap = act + ((size_t)b * TLEN + t0) * CDIM + tid;
    int cnt = 0;
    if (j >= 0) {
#pragma unroll 1
        for (int p = 0; p < 8; p++) {
            int vr[8];
#pragma unroll
            for (int u = 0; u < 8; u++)          // 8 coalesced loads in flight
                vr[u] = ap[(size_t)(p * 8 + u) * CDIM];
#pragma unroll
            for (int u = 0; u < 8; u++) {
                bool on = vr[u] != 0;
                m[j][p * 8 + u] = on ? one : zero;
                cnt += on;
            }
        }
        if (cnt) atomicAdd(&g_counts[tid], cnt);
    }
    __syncthreads();

    int lid = tid & 31, wid = tid >> 5;
    for (int jj = wid; jj < nact; jj += 8) {
        uint32_t v = *(const uint32_t*)&m[jj][2 * lid];
        *(uint32_t*)((char*)g_Amat +
                     ((size_t)(b * MPAD + jj) * TLEN + t0 + 2 * lid) * 2) = v;
    }
}

// ---------------------------------------------------------------------------
// Static-NT compute body (warp tile m32 x n32): per ks, 2 A ldsm + NB B ldsm
// + 2*NT mma. NT compile-time -> clean static scheduling.
// ---------------------------------------------------------------------------
template <int NT>
__device__ __forceinline__ void compute_t(uint32_t mask_base, uint32_t feat_base,
                                          const uint32_t* a_off,
                                          const uint32_t* b_off,
                                          float acc[2][4][4]) {
    constexpr int NB = (NT + 1) >> 1;
#pragma unroll
    for (int ks = 0; ks < 4; ks++) {
        uint32_t a[2][4], bf[NB][4];
#pragma unroll
        for (int mt = 0; mt < 2; mt++)
            ldmatrix_x4(a[mt], feat_base + sw128(a_off[mt] + ks * 32));
#pragma unroll
        for (int nb = 0; nb < NB; nb++)
            ldmatrix_x4(bf[nb], mask_base + sw128(b_off[nb] + ks * 32));
#pragma unroll
        for (int mt = 0; mt < 2; mt++)
#pragma unroll
            for (int nt = 0; nt < NT; nt++)
                mma16816(acc[mt][nt], a[mt],
                         bf[nt >> 1][(nt & 1) * 2], bf[nt >> 1][(nt & 1) * 2 + 1]);
    }
}

// ---------------------------------------------------------------------------
// Stage 2: per-batch bf16 GEMM — R16 ordering with super-chunks (2 sub-chunks
// per stage, one barrier per super-chunk). Single fst[16] buffer: every
// ldg -> store_b pair is separated by a full compute (no R15 stall, no R14
// register growth).
// ---------------------------------------------------------------------------
__global__ __launch_bounds__(512, 1) void gemm_kernel(const float* __restrict__ feats) {
    int task, ck0, nsup;
    if (blockIdx.x < NFULL) {
        task = blockIdx.x;           ck0 = 0;                 nsup = 16;
    } else {
        int r = blockIdx.x - NFULL;
        task = NFULL + (r >> 2);     ck0 = (r & 3) * QCHUNKS; nsup = QCHUNKS / 2;
    }
    const int b = task & 15;
    const int d0 = (task >> 4) * NTILE;
    const int nbase = blockIdx.y * 128;     // class window base (2nd CTA rare)
    const int nact = g_nact[b];
    if (nbase >= nact) return;
    const int nlim = nact - nbase;          // classes in this CTA's window

    extern __shared__ char smem[];
    const uint32_t sb = smem_u32(smem);
    const int tid = threadIdx.x;
    const int lane = tid & 31, wid = tid >> 5;
    const int wm = wid & 3;             // m: d rows wm*32 (dense) — SMSP id
    const int wn = wid >> 2;            // n: class cols wn*32

    const int nrem = nlim - wn * 32;
    const int ncap = nrem < 32 ? (nrem > 0 ? nrem : 0) : 32;
    const int ntmax = (ncap + 7) >> 3;          // 0..4

    const int dcol = tid & 127;
    const int kq = tid >> 7;            // 0..3 -> k = kq*16 .. +15

    float acc[2][4][4];
#pragma unroll
    for (int mt = 0; mt < 2; mt++)
#pragma unroll
        for (int i = 0; i < 4; i++)
#pragma unroll
            for (int r = 0; r < 4; r++) acc[mt][i][r] = 0.0f;

    uint32_t a_off[2];
#pragma unroll
    for (int mt = 0; mt < 2; mt++) {
        int rowA = wm * 32 + mt * 16 + (lane & 15);
        a_off[mt] = (uint32_t)(rowA * 128 + (lane >> 4) * 16);
    }
    uint32_t b_off[2];
#pragma unroll
    for (int nb = 0; nb < 2; nb++) {
        int rowB = wn * 32 + nb * 16 + ((lane >> 4) << 3) + (lane & 7);
        b_off[nb] = (uint32_t)(rowB * 128 + ((lane >> 3) & 1) * 16);
    }

    const __nv_bfloat16* abase_g = g_Amat + (size_t)(b * MPAD + nbase) * TLEN;
    const float* fbase = feats + (size_t)b * TLEN * DDIM;

    float fst[16];   // feats staging, single buffer (one chunk)

    auto cpA2 = [&](int ck, int st) {    // mask: chunks ck, ck+1 -> stage st
        const uint32_t abase = sb + SM_MASK(st);
#pragma unroll
        for (int sub = 0; sub < 2; sub++) {
            const int k0 = (ck + sub) * KC;
#pragma unroll
            for (int it = 0; it < 2; it++) {
                int idx = it * 512 + tid;
                int row = idx >> 3, seg = idx & 7;
                if (row < nlim) {
                    const void* g = abase_g + (size_t)row * TLEN + k0 + seg * 8;
                    cp_async16(abase + sub * 16384 +
                               sw128((uint32_t)(row * 128 + seg * 16)), g);
                }
            }
        }
        cp_commit();
    };
    auto ldg_fst = [&](int ck) {         // feats LDG (one chunk) -> fst
        const float* fp = fbase + (size_t)(ck * KC + kq * 16) * DDIM + d0 + dcol;
#pragma unroll
        for (int jj = 0; jj < 16; jj++) fst[jj] = fp[(size_t)jj * DDIM];
    };
    auto store_b = [&](int st, int sub) {  // cvt fst -> STS into stage/sub
        const uint32_t bbase = sb + SM_FEAT(st) + sub * 16384;
        uint32_t p[8];
#pragma unroll
        for (int jj = 0; jj < 8; jj++)
            p[jj] = pack_bf16x2(fst[2 * jj], fst[2 * jj + 1]);
        uint32_t o0 = (uint32_t)(dcol * 128 + kq * 32);
        sts128(bbase + sw128(o0), p[0], p[1], p[2], p[3]);
        sts128(bbase + sw128(o0 + 16), p[4], p[5], p[6], p[7]);
    };
    auto compute = [&](int st, int sub) {
        const uint32_t mask_base = sb + SM_MASK(st) + sub * 16384;
        const uint32_t feat_base = sb + SM_FEAT(st) + sub * 16384;
        switch (ntmax) {
            case 4: compute_t<4>(mask_base, feat_base, a_off, b_off, acc); break;
            case 3: compute_t<3>(mask_base, feat_base, a_off, b_off, acc); break;
            case 2: compute_t<2>(mask_base, feat_base, a_off, b_off, acc); break;
            case 1: compute_t<1>(mask_base, feat_base, a_off, b_off, acc); break;
            default: break;
        }
    };

    // prologue: super-chunk 0 fully staged (two one-time fst stalls)
    ldg_fst(ck0);
    cpA2(ck0, 0);
    store_b(0, 0);               // stalls on fst(ck0) — once
    ldg_fst(ck0 + 1);
    store_b(0, 1);               // stalls on fst(ck0+1) — once (prologue only)
    if (nsup > 1) ldg_fst(ck0 + 2);
    cp_wait0();
    __syncthreads();

#pragma unroll 1
    for (int i = 0; i < nsup; i++) {
        const int s = i & 1;
        if (i + 1 < nsup) {
            store_b(s ^ 1, 0);               // fst = chunk ck0+2(i+1), loaded prev iter
            cpA2(ck0 + 2 * (i + 1), s ^ 1);  // mask for next super-chunk
            ldg_fst(ck0 + 2 * (i + 1) + 1);  // second sub of next super
        }
        compute(s, 0);
        if (i + 1 < nsup) {
            store_b(s ^ 1, 1);               // gap = compute(s,0) since its ldg
            if (i + 2 < nsup) ldg_fst(ck0 + 2 * (i + 2));
        }
        compute(s, 1);
        if (i + 1 < nsup) {
            cp_wait0();
            __syncthreads();
        }
    }

    // epilogue: fragment rows = d (dense), cols = compact classes -> scatter
    {
        const int col2 = (lane & 3) * 2;
        const int* clist = g_clist + b * MPAD;
#pragma unroll
        for (int mt = 0; mt < 2; mt++) {
            const int dd = d0 + wm * 32 + mt * 16 + (lane >> 2);
#pragma unroll
            for (int nt = 0; nt < 4; nt++) {
                if (nt >= ntmax) break;
                int jn = nbase + wn * 32 + nt * 8 + col2;
                int c0 = (jn < nact) ? clist[jn] : -1;
                int c1 = (jn + 1 < nact) ? clist[jn + 1] : -1;
                if (c0 >= 0) {
                    float* gp = g_sums + (size_t)c0 * DDIM + dd;
                    atomicAdd(gp, acc[mt][nt][0]);
                    atomicAdd(gp + 8, acc[mt][nt][2]);
                }
                if (c1 >= 0) {
                    float* gp = g_sums + (size_t)c1 * DDIM + dd;
                    atomicAdd(gp, acc[mt][nt][1]);
                    atomicAdd(gp + 8, acc[mt][nt][3]);
                }
            }
        }
    }
}

// ---------------------------------------------------------------------------
// Stage 3: momentum update — 2 independent float4 chains per thread (ILP)
// ---------------------------------------------------------------------------
#define FIN_HALF (CDIM * DDIM / 4 / 2)   // 51200
__global__ void finalize_kernel(const float4* __restrict__ proto,
                                float4* __restrict__ out) {
    int i = blockIdx.x * 256 + threadIdx.x;
    if (i >= FIN_HALF) return;
    int i2 = i + FIN_HALF;
    int ca = i >> 9, cb = i2 >> 9;
    float4 pa = proto[i], pb = proto[i2];
    float4 sa = ((const float4*)g_sums)[i], sb = ((const float4*)g_sums)[i2];
    int na = g_counts[ca], nb = g_counts[cb];
    float ia = 0.001f / fmaxf((float)na, 1.0f);
    float ib = 0.001f / fmaxf((float)nb, 1.0f);
    float4 ra, rb;
    ra.x = 0.999f * pa.x + sa.x * ia;  ra.y = 0.999f * pa.y + sa.y * ia;
    ra.z = 0.999f * pa.z + sa.z * ia;  ra.w = 0.999f * pa.w + sa.w * ia;
    rb.x = 0.999f * pb.x + sb.x * ib;  rb.y = 0.999f * pb.y + sb.y * ib;
    rb.z = 0.999f * pb.z + sb.z * ib;  rb.w = 0.999f * pb.w + sb.w * ib;
    out[i]  = (na > 0) ? ra : pa;
    out[i2] = (nb > 0) ? rb : pb;
}

// ---------------------------------------------------------------------------
// Launch
// ---------------------------------------------------------------------------
extern "C" void kernel_launch(void* const* d_in, const int* in_sizes, int n_in,
                              void* d_out, int out_size) {
    const float* feats = (const float*)d_in[0];
    const int* act = (const int*)d_in[1];
    const int* vid = (const int*)d_in[2];
    const float* proto = (const float*)d_in[3];
    float* out = (float*)d_out;

    cudaFuncSetAttribute(gemm_kernel, cudaFuncAttributeMaxDynamicSharedMemorySize,
                         SMEM_BYTES);

    prep_kernel<<<PREP_BLOCKS, 256>>>(vid);
    build_mask_kernel<<<BATCH * (TLEN / 64), 256>>>(act);
    gemm_kernel<<<dim3(NFULL + NQUART, 2), 512, SMEM_BYTES>>>(feats);
    finalize_kernel<<<(FIN_HALF + 255) / 256, 256>>>(
        (const float4*)proto, (float4*)out);
}